// round 12
// baseline (speedup 1.0000x reference)
#include <cuda_runtime.h>

#define NGROUPS 8
#define THREADS 256
#define NBLOCKS 740                   // one full wave at 5 CTAs/SM (48-reg class)
#define MAX_BLOCKS 2048

// Scratch (no allocations allowed). g_part fully overwritten each run;
// g_counter reset to 0 by the last block (deterministic across replays).
__device__ float    g_part[MAX_BLOCKS * 2 * NGROUPS];
__device__ unsigned g_counter = 0;

__device__ __forceinline__ void block_reduce_16(float* s, float* c,
                                                float* red /* [THREADS/32][16] */) {
#pragma unroll
    for (int j = 0; j < NGROUPS; j++) {
#pragma unroll
        for (int o = 16; o > 0; o >>= 1) {
            s[j] += __shfl_down_sync(0xffffffffu, s[j], o);
            c[j] += __shfl_down_sync(0xffffffffu, c[j], o);
        }
    }
    int lane = threadIdx.x & 31;
    int warp = threadIdx.x >> 5;
    if (lane == 0) {
#pragma unroll
        for (int j = 0; j < NGROUPS; j++) {
            red[warp * 16 + j]           = s[j];
            red[warp * 16 + NGROUPS + j] = c[j];
        }
    }
    __syncthreads();
    if (threadIdx.x < 2 * NGROUPS) {
        float t = 0.0f;
#pragma unroll
        for (int w = 0; w < THREADS / 32; w++) t += red[w * 16 + threadIdx.x];
        red[threadIdx.x] = t;   // result lives in red[0..15]
    }
    __syncthreads();
}

__global__ __launch_bounds__(THREADS) void fused_kernel(
    const float* __restrict__ in, const int* __restrict__ tgt,
    const int* __restrict__ grp, float* __restrict__ out, int n)
{
    __shared__ float red[(THREADS / 32) * 16];
    __shared__ bool  is_last;

    float s[NGROUPS], c[NGROUPS];
#pragma unroll
    for (int j = 0; j < NGROUPS; j++) { s[j] = 0.0f; c[j] = 0.0f; }

    int tid = blockIdx.x * blockDim.x + threadIdx.x;
    int total = gridDim.x * blockDim.x;

    // Rolling loop over PAIRS of rows: one int2 load each for tgt/grp
    // (halves index-load instrs), two independent gathers per iteration
    // (64B apart -> same 128B L2 line). unroll 4 => 8 gathers in flight.
    int npair = n >> 1;
#pragma unroll 4
    for (int p = tid; p < npair; p += total) {
        int2 t2 = __ldcs((const int2*)tgt + p);
        int2 g2 = __ldcs((const int2*)grp + p);
        size_t row0 = (size_t)p << 5;               // (2p) * 16
        float v0 = __ldcs(in + row0 + t2.x);
        float v1 = __ldcs(in + row0 + 16 + t2.y);
        float e0 = fabsf(1.0f - v0);
        float e1 = fabsf(1.0f - v1);
#pragma unroll
        for (int j = 0; j < NGROUPS; j++) {
            bool m0 = (g2.x == j);
            bool m1 = (g2.y == j);
            s[j] += m0 ? e0 : 0.0f;
            s[j] += m1 ? e1 : 0.0f;
            c[j] += m0 ? 1.0f : 0.0f;   // exact in f32 (< 2^24)
            c[j] += m1 ? 1.0f : 0.0f;
        }
    }
    // Odd tail row (n odd): handled by thread 0 of block 0
    if ((n & 1) && tid == 0) {
        int i = n - 1;
        int t = tgt[i];
        int g = grp[i];
        float e = fabsf(1.0f - in[(size_t)i * 16 + t]);
#pragma unroll
        for (int j = 0; j < NGROUPS; j++) {
            bool m = (g == j);
            s[j] += m ? e : 0.0f;
            c[j] += m ? 1.0f : 0.0f;
        }
    }

    block_reduce_16(s, c, red);

    if (threadIdx.x < 2 * NGROUPS)
        g_part[blockIdx.x * 2 * NGROUPS + threadIdx.x] = red[threadIdx.x];
    __syncthreads();

    if (threadIdx.x == 0) {
        __threadfence();
        unsigned v = atomicAdd(&g_counter, 1u);
        is_last = (v == gridDim.x - 1);
    }
    __syncthreads();
    if (!is_last) return;

    // Final reduction over per-block partials (L2-hot, 740*16 floats)
    float fs[NGROUPS], fc[NGROUPS];
#pragma unroll
    for (int j = 0; j < NGROUPS; j++) { fs[j] = 0.0f; fc[j] = 0.0f; }
    for (int b = threadIdx.x; b < gridDim.x; b += THREADS) {
#pragma unroll
        for (int j = 0; j < NGROUPS; j++) {
            fs[j] += g_part[b * 2 * NGROUPS + j];
            fc[j] += g_part[b * 2 * NGROUPS + NGROUPS + j];
        }
    }
    __syncthreads();
    block_reduce_16(fs, fc, red);

    if (threadIdx.x == 0) {
        float msum = 0.0f;
#pragma unroll
        for (int j = 0; j < NGROUPS; j++) {
            float cnt = red[NGROUPS + j];
            msum += (cnt > 0.0f) ? (red[j] / cnt) : 0.0f;
        }
        out[0] = fabsf(0.5f - msum * (1.0f / NGROUPS));
        g_counter = 0;   // reset for next graph replay
    }
}

extern "C" void kernel_launch(void* const* d_in, const int* in_sizes, int n_in,
                              void* d_out, int out_size) {
    const float* in  = (const float*)d_in[0];
    const int*   tgt = (const int*)d_in[1];
    const int*   grp = (const int*)d_in[2];
    float*       out = (float*)d_out;
    int n = in_sizes[1];  // N rows

    int blocks = NBLOCKS;
    int maxb = ((n >> 1) + THREADS - 1) / THREADS;
    if (blocks > maxb) blocks = maxb;
    if (blocks > MAX_BLOCKS) blocks = MAX_BLOCKS;
    if (blocks < 1) blocks = 1;
    fused_kernel<<<blocks, THREADS>>>(in, tgt, grp, out, n);
}

// round 13
// speedup vs baseline: 1.0513x; 1.0513x over previous
#include <cuda_runtime.h>

#define NGROUPS 8
#define THREADS 256
#define NBLOCKS 592                   // one full wave at 4 CTAs/SM (56-64 reg class)
#define MAX_BLOCKS 2048

// Scratch (no allocations allowed). g_part fully overwritten each run;
// g_counter reset to 0 by the last block (deterministic across replays).
__device__ float    g_part[MAX_BLOCKS * 2 * NGROUPS];
__device__ unsigned g_counter = 0;

__device__ __forceinline__ void block_reduce_16(float* s, float* c,
                                                float* red /* [THREADS/32][16] */) {
#pragma unroll
    for (int j = 0; j < NGROUPS; j++) {
#pragma unroll
        for (int o = 16; o > 0; o >>= 1) {
            s[j] += __shfl_down_sync(0xffffffffu, s[j], o);
            c[j] += __shfl_down_sync(0xffffffffu, c[j], o);
        }
    }
    int lane = threadIdx.x & 31;
    int warp = threadIdx.x >> 5;
    if (lane == 0) {
#pragma unroll
        for (int j = 0; j < NGROUPS; j++) {
            red[warp * 16 + j]           = s[j];
            red[warp * 16 + NGROUPS + j] = c[j];
        }
    }
    __syncthreads();
    if (threadIdx.x < 2 * NGROUPS) {
        float t = 0.0f;
#pragma unroll
        for (int w = 0; w < THREADS / 32; w++) t += red[w * 16 + threadIdx.x];
        red[threadIdx.x] = t;   // result lives in red[0..15]
    }
    __syncthreads();
}

__global__ __launch_bounds__(THREADS) void fused_kernel(
    const float* __restrict__ in, const int* __restrict__ tgt,
    const int* __restrict__ grp, float* __restrict__ out, int n)
{
    __shared__ float red[(THREADS / 32) * 16];
    __shared__ bool  is_last;

    float s[NGROUPS], c[NGROUPS];
#pragma unroll
    for (int j = 0; j < NGROUPS; j++) { s[j] = 0.0f; c[j] = 0.0f; }

    int tid = blockIdx.x * blockDim.x + threadIdx.x;
    int total = gridDim.x * blockDim.x;

    // Rolling loop over QUADS of rows: one int4 load each for tgt/grp per
    // 4 rows (quarter the index instrs), 4 independent gathers spanning
    // 256 contiguous bytes. unroll 2 => 8 gathers in flight per thread.
    int nquad = n >> 2;
#pragma unroll 2
    for (int q = tid; q < nquad; q += total) {
        int4 t4 = __ldcs((const int4*)tgt + q);
        int4 g4 = __ldcs((const int4*)grp + q);
        size_t row0 = (size_t)q << 6;               // (4q) * 16
        float v0 = __ldcs(in + row0      + t4.x);
        float v1 = __ldcs(in + row0 + 16 + t4.y);
        float v2 = __ldcs(in + row0 + 32 + t4.z);
        float v3 = __ldcs(in + row0 + 48 + t4.w);
        float e0 = fabsf(1.0f - v0);
        float e1 = fabsf(1.0f - v1);
        float e2 = fabsf(1.0f - v2);
        float e3 = fabsf(1.0f - v3);
#pragma unroll
        for (int j = 0; j < NGROUPS; j++) {
            bool m0 = (g4.x == j);
            bool m1 = (g4.y == j);
            bool m2 = (g4.z == j);
            bool m3 = (g4.w == j);
            s[j] += m0 ? e0 : 0.0f;
            s[j] += m1 ? e1 : 0.0f;
            s[j] += m2 ? e2 : 0.0f;
            s[j] += m3 ? e3 : 0.0f;
            c[j] += m0 ? 1.0f : 0.0f;   // exact in f32 (< 2^24)
            c[j] += m1 ? 1.0f : 0.0f;
            c[j] += m2 ? 1.0f : 0.0f;
            c[j] += m3 ? 1.0f : 0.0f;
        }
    }
    // Tail rows (n % 4): handled by thread 0 of block 0
    if (tid == 0) {
        for (int i = nquad << 2; i < n; i++) {
            int t = tgt[i];
            int g = grp[i];
            float e = fabsf(1.0f - in[(size_t)i * 16 + t]);
#pragma unroll
            for (int j = 0; j < NGROUPS; j++) {
                bool m = (g == j);
                s[j] += m ? e : 0.0f;
                c[j] += m ? 1.0f : 0.0f;
            }
        }
    }

    block_reduce_16(s, c, red);

    if (threadIdx.x < 2 * NGROUPS)
        g_part[blockIdx.x * 2 * NGROUPS + threadIdx.x] = red[threadIdx.x];
    __syncthreads();

    if (threadIdx.x == 0) {
        __threadfence();
        unsigned v = atomicAdd(&g_counter, 1u);
        is_last = (v == gridDim.x - 1);
    }
    __syncthreads();
    if (!is_last) return;

    // Final reduction over per-block partials (L2-hot, 592*16 floats)
    float fs[NGROUPS], fc[NGROUPS];
#pragma unroll
    for (int j = 0; j < NGROUPS; j++) { fs[j] = 0.0f; fc[j] = 0.0f; }
    for (int b = threadIdx.x; b < gridDim.x; b += THREADS) {
#pragma unroll
        for (int j = 0; j < NGROUPS; j++) {
            fs[j] += g_part[b * 2 * NGROUPS + j];
            fc[j] += g_part[b * 2 * NGROUPS + NGROUPS + j];
        }
    }
    __syncthreads();
    block_reduce_16(fs, fc, red);

    if (threadIdx.x == 0) {
        float msum = 0.0f;
#pragma unroll
        for (int j = 0; j < NGROUPS; j++) {
            float cnt = red[NGROUPS + j];
            msum += (cnt > 0.0f) ? (red[j] / cnt) : 0.0f;
        }
        out[0] = fabsf(0.5f - msum * (1.0f / NGROUPS));
        g_counter = 0;   // reset for next graph replay
    }
}

extern "C" void kernel_launch(void* const* d_in, const int* in_sizes, int n_in,
                              void* d_out, int out_size) {
    const float* in  = (const float*)d_in[0];
    const int*   tgt = (const int*)d_in[1];
    const int*   grp = (const int*)d_in[2];
    float*       out = (float*)d_out;
    int n = in_sizes[1];  // N rows

    int blocks = NBLOCKS;
    int maxb = ((n >> 2) + THREADS - 1) / THREADS;
    if (blocks > maxb) blocks = maxb;
    if (blocks > MAX_BLOCKS) blocks = MAX_BLOCKS;
    if (blocks < 1) blocks = 1;
    fused_kernel<<<blocks, THREADS>>>(in, tgt, grp, out, n);
}

// round 14
// speedup vs baseline: 1.0588x; 1.0072x over previous
#include <cuda_runtime.h>

#define NGROUPS 8
#define THREADS 256
#define NBLOCKS 592                   // one full wave at 4 CTAs/SM
#define MAX_BLOCKS 2048

// Scratch (no allocations allowed). g_part fully overwritten each run;
// g_counter reset to 0 by the last block (deterministic across replays).
__device__ float    g_part[MAX_BLOCKS * 2 * NGROUPS];
__device__ unsigned g_counter = 0;

__device__ __forceinline__ void block_reduce_16(float* s, float* c,
                                                float* red /* [THREADS/32][16] */) {
#pragma unroll
    for (int j = 0; j < NGROUPS; j++) {
#pragma unroll
        for (int o = 16; o > 0; o >>= 1) {
            s[j] += __shfl_down_sync(0xffffffffu, s[j], o);
            c[j] += __shfl_down_sync(0xffffffffu, c[j], o);
        }
    }
    int lane = threadIdx.x & 31;
    int warp = threadIdx.x >> 5;
    if (lane == 0) {
#pragma unroll
        for (int j = 0; j < NGROUPS; j++) {
            red[warp * 16 + j]           = s[j];
            red[warp * 16 + NGROUPS + j] = c[j];
        }
    }
    __syncthreads();
    if (threadIdx.x < 2 * NGROUPS) {
        float t = 0.0f;
#pragma unroll
        for (int w = 0; w < THREADS / 32; w++) t += red[w * 16 + threadIdx.x];
        red[threadIdx.x] = t;   // result lives in red[0..15]
    }
    __syncthreads();
}

__global__ __launch_bounds__(THREADS) void fused_kernel(
    const float* __restrict__ in, const int* __restrict__ tgt,
    const int* __restrict__ grp, float* __restrict__ out, int n)
{
    __shared__ float red[(THREADS / 32) * 16];
    __shared__ bool  is_last;

    float s[NGROUPS], c[NGROUPS];
#pragma unroll
    for (int j = 0; j < NGROUPS; j++) { s[j] = 0.0f; c[j] = 0.0f; }

    int tid = blockIdx.x * blockDim.x + threadIdx.x;
    int total = gridDim.x * blockDim.x;

    // Quad rows per iteration, unroll 4 => up to 16 independent gathers +
    // 8 int4 index loads in flight per thread. This is the only axis that
    // has moved DRAM efficiency (R9 scalar:5593, R12/13 x8:5700).
    int nquad = n >> 2;
#pragma unroll 4
    for (int q = tid; q < nquad; q += total) {
        int4 t4 = __ldcs((const int4*)tgt + q);
        int4 g4 = __ldcs((const int4*)grp + q);
        size_t row0 = (size_t)q << 6;               // (4q) * 16
        float v0 = __ldcs(in + row0      + t4.x);
        float v1 = __ldcs(in + row0 + 16 + t4.y);
        float v2 = __ldcs(in + row0 + 32 + t4.z);
        float v3 = __ldcs(in + row0 + 48 + t4.w);
        float e0 = fabsf(1.0f - v0);
        float e1 = fabsf(1.0f - v1);
        float e2 = fabsf(1.0f - v2);
        float e3 = fabsf(1.0f - v3);
#pragma unroll
        for (int j = 0; j < NGROUPS; j++) {
            bool m0 = (g4.x == j);
            bool m1 = (g4.y == j);
            bool m2 = (g4.z == j);
            bool m3 = (g4.w == j);
            s[j] += m0 ? e0 : 0.0f;
            s[j] += m1 ? e1 : 0.0f;
            s[j] += m2 ? e2 : 0.0f;
            s[j] += m3 ? e3 : 0.0f;
            c[j] += m0 ? 1.0f : 0.0f;   // exact in f32 (< 2^24)
            c[j] += m1 ? 1.0f : 0.0f;
            c[j] += m2 ? 1.0f : 0.0f;
            c[j] += m3 ? 1.0f : 0.0f;
        }
    }
    // Tail rows (n % 4): thread 0 of block 0
    if (tid == 0) {
        for (int i = nquad << 2; i < n; i++) {
            int t = tgt[i];
            int g = grp[i];
            float e = fabsf(1.0f - in[(size_t)i * 16 + t]);
#pragma unroll
            for (int j = 0; j < NGROUPS; j++) {
                bool m = (g == j);
                s[j] += m ? e : 0.0f;
                c[j] += m ? 1.0f : 0.0f;
            }
        }
    }

    block_reduce_16(s, c, red);

    if (threadIdx.x < 2 * NGROUPS)
        g_part[blockIdx.x * 2 * NGROUPS + threadIdx.x] = red[threadIdx.x];
    __syncthreads();

    if (threadIdx.x == 0) {
        __threadfence();
        unsigned v = atomicAdd(&g_counter, 1u);
        is_last = (v == gridDim.x - 1);
    }
    __syncthreads();
    if (!is_last) return;

    // Final reduction over per-block partials (L2-hot)
    float fs[NGROUPS], fc[NGROUPS];
#pragma unroll
    for (int j = 0; j < NGROUPS; j++) { fs[j] = 0.0f; fc[j] = 0.0f; }
    for (int b = threadIdx.x; b < gridDim.x; b += THREADS) {
#pragma unroll
        for (int j = 0; j < NGROUPS; j++) {
            fs[j] += g_part[b * 2 * NGROUPS + j];
            fc[j] += g_part[b * 2 * NGROUPS + NGROUPS + j];
        }
    }
    __syncthreads();
    block_reduce_16(fs, fc, red);

    if (threadIdx.x == 0) {
        float msum = 0.0f;
#pragma unroll
        for (int j = 0; j < NGROUPS; j++) {
            float cnt = red[NGROUPS + j];
            msum += (cnt > 0.0f) ? (red[j] / cnt) : 0.0f;
        }
        out[0] = fabsf(0.5f - msum * (1.0f / NGROUPS));
        g_counter = 0;   // reset for next graph replay
    }
}

extern "C" void kernel_launch(void* const* d_in, const int* in_sizes, int n_in,
                              void* d_out, int out_size) {
    const float* in  = (const float*)d_in[0];
    const int*   tgt = (const int*)d_in[1];
    const int*   grp = (const int*)d_in[2];
    float*       out = (float*)d_out;
    int n = in_sizes[1];  // N rows

    int blocks = NBLOCKS;
    int maxb = ((n >> 2) + THREADS - 1) / THREADS;
    if (blocks > maxb) blocks = maxb;
    if (blocks > MAX_BLOCKS) blocks = MAX_BLOCKS;
    if (blocks < 1) blocks = 1;
    fused_kernel<<<blocks, THREADS>>>(in, tgt, grp, out, n);
}